// round 5
// baseline (speedup 1.0000x reference)
#include <cuda_runtime.h>
#include <cstdint>

#define M_TOT 8192
#define EMBD  1024
#define TSEQ  2048
#define NB    4
#define NH    16
#define HDI   64

// Scratch
__device__ float g_q[M_TOT * EMBD];
__device__ float g_k[M_TOT * EMBD];
__device__ float g_v[M_TOT * EMBD];
__device__ float g_attn[M_TOT * EMBD];

__device__ __forceinline__ unsigned f2tf(float f) {
    unsigned r; asm("cvt.rna.tf32.f32 %0, %1;" : "=r"(r) : "f"(f)); return r;
}

// D += A*B, m16n8k8 tf32, D==C in place
__device__ __forceinline__ void mma8(float* d, const unsigned* a, const unsigned* b) {
    asm volatile("mma.sync.aligned.m16n8k8.row.col.f32.tf32.tf32.f32 "
        "{%0,%1,%2,%3}, {%4,%5,%6,%7}, {%8,%9}, {%0,%1,%2,%3};"
        : "+f"(d[0]), "+f"(d[1]), "+f"(d[2]), "+f"(d[3])
        : "r"(a[0]), "r"(a[1]), "r"(a[2]), "r"(a[3]), "r"(b[0]), "r"(b[1]));
}

// ===========================================================================
// tf32 GEMM: Y = X @ W^T + bias.  128x128x32 tiles, 256 thr, 8 warps (4m x 2n).
// Smem holds operands in MMA-FRAGMENT layout:
//   A: [mtile(8)][ks(4)][lane(32)] x 4 words  (LDS.128 per fragment)
//   B: [ntile(16)][ks(4)][lane(32)] x 2 words (LDS.64 per fragment)
// Double buffered, one __syncthreads per k-chunk.
// ===========================================================================
#define GEMM_SMEM (2 * 32768)

template<int SCATTER>
__device__ __forceinline__ void gemm_body(
    const float* __restrict__ A, const float* __restrict__ Bw,
    const float* __restrict__ bias, float* __restrict__ out,
    int bx, int by)
{
    extern __shared__ unsigned smu[];   // [2][8192] words per stage

    const int tid  = threadIdx.x;
    const int lane = tid & 31, wid = tid >> 5;
    const int wmt = (wid & 3) * 2;      // first mtile of warp
    const int wnt = (wid >> 2) * 8;     // first ntile of warp
    const int m0 = bx * 128, n0 = by * 128;

    // Staging geometry: thread covers row=tid>>1, 16 cols at (tid&1)*16.
    const int row = tid >> 1, cg = (tid & 1) * 16;
    const float* gA = A  + (size_t)(m0 + row) * EMBD + cg;
    const float* gB = Bw + (size_t)(n0 + row) * EMBD + cg;

    // Precomputed word offsets (element j adds j*4 for A, j*2 for B)
    unsigned abase[4], bbase[4];
#pragma unroll
    for (int i = 0; i < 4; i++) {
        int c = cg + 4 * i;
        int ks = (c >> 3) & 3, h = (c >> 2) & 1;
        abase[i] = ((row >> 4) * 4 + ks) * 128 + (row & 7) * 16 + h * 2 + ((row >> 3) & 1);
        bbase[i] = 4096 + ((row >> 3) * 4 + ks) * 64 + (row & 7) * 8 + h;
    }

    float4 ra[4], rb[4];
#pragma unroll
    for (int i = 0; i < 4; i++) { ra[i] = *(const float4*)(gA + 4 * i);
                                  rb[i] = *(const float4*)(gB + 4 * i); }
    // STS chunk 0 -> buf 0
#pragma unroll
    for (int i = 0; i < 4; i++) {
        unsigned* pa = smu + abase[i];
        pa[0] = f2tf(ra[i].x); pa[4] = f2tf(ra[i].y);
        pa[8] = f2tf(ra[i].z); pa[12] = f2tf(ra[i].w);
        unsigned* pb = smu + bbase[i];
        pb[0] = f2tf(rb[i].x); pb[2] = f2tf(rb[i].y);
        pb[4] = f2tf(rb[i].z); pb[6] = f2tf(rb[i].w);
    }
    __syncthreads();

    float acc[2][8][4];
#pragma unroll
    for (int mt = 0; mt < 2; mt++)
#pragma unroll
        for (int nt = 0; nt < 8; nt++)
#pragma unroll
            for (int f = 0; f < 4; f++) acc[mt][nt][f] = 0.f;

    for (int c = 0; c < 32; c++) {
        const int b = c & 1;
        if (c < 31) {
            const float* nA = gA + (c + 1) * 32;
            const float* nB = gB + (c + 1) * 32;
#pragma unroll
            for (int i = 0; i < 4; i++) { ra[i] = *(const float4*)(nA + 4 * i);
                                          rb[i] = *(const float4*)(nB + 4 * i); }
        }
        const uint4* Av = (const uint4*)(smu + b * 8192);
        const uint2* Bv = (const uint2*)(smu + b * 8192 + 4096);
#pragma unroll
        for (int ks = 0; ks < 4; ks++) {
            uint4 a0 = Av[((wmt + 0) * 4 + ks) * 32 + lane];
            uint4 a1 = Av[((wmt + 1) * 4 + ks) * 32 + lane];
            unsigned af0[4] = {a0.x, a0.y, a0.z, a0.w};
            unsigned af1[4] = {a1.x, a1.y, a1.z, a1.w};
#pragma unroll
            for (int nt = 0; nt < 8; nt++) {
                uint2 bb = Bv[((wnt + nt) * 4 + ks) * 32 + lane];
                unsigned bf[2] = {bb.x, bb.y};
                mma8(acc[0][nt], af0, bf);
                mma8(acc[1][nt], af1, bf);
            }
        }
        if (c < 31) {
            unsigned* dst = smu + ((c + 1) & 1) * 8192;
#pragma unroll
            for (int i = 0; i < 4; i++) {
                unsigned* pa = dst + abase[i];
                pa[0] = f2tf(ra[i].x); pa[4] = f2tf(ra[i].y);
                pa[8] = f2tf(ra[i].z); pa[12] = f2tf(ra[i].w);
                unsigned* pb = dst + bbase[i];
                pb[0] = f2tf(rb[i].x); pb[2] = f2tf(rb[i].y);
                pb[4] = f2tf(rb[i].z); pb[6] = f2tf(rb[i].w);
            }
        }
        __syncthreads();
    }

    // Epilogue
    const int g = lane >> 2, t = lane & 3;
#pragma unroll
    for (int mt = 0; mt < 2; mt++) {
        int rbase = m0 + (wmt + mt) * 16 + g;
#pragma unroll
        for (int half = 0; half < 2; half++) {
            int r = rbase + half * 8;
            int bb2 = r >> 11, tt = r & 2047;
#pragma unroll
            for (int nt = 0; nt < 8; nt++) {
                int ccol = n0 + (wnt + nt) * 8 + 2 * t;
                float v0 = acc[mt][nt][half * 2 + 0] + bias[ccol];
                float v1 = acc[mt][nt][half * 2 + 1] + bias[ccol + 1];
                if (SCATTER) {
                    int h = ccol >> 6, d = ccol & 63;
                    *(float2*)(out + ((size_t)((bb2 * NH + h) * TSEQ + tt)) * HDI + d)
                        = make_float2(v0, v1);
                } else {
                    *(float2*)(out + (size_t)r * EMBD + ccol) = make_float2(v0, v1);
                }
            }
        }
    }
}

__global__ __launch_bounds__(256) void qkv_kernel(
    const float* __restrict__ X,
    const float* __restrict__ Wq, const float* __restrict__ bq,
    const float* __restrict__ Wk, const float* __restrict__ bk,
    const float* __restrict__ Wv, const float* __restrict__ bv)
{
    const float* W; const float* bias; float* out;
    if (blockIdx.z == 0)      { W = Wq; bias = bq; out = g_q; }
    else if (blockIdx.z == 1) { W = Wk; bias = bk; out = g_k; }
    else                      { W = Wv; bias = bv; out = g_v; }
    gemm_body<1>(X, W, bias, out, blockIdx.x, blockIdx.y);
}

__global__ __launch_bounds__(256) void proj_kernel(
    const float* __restrict__ Wo, const float* __restrict__ bo,
    float* __restrict__ out)
{
    gemm_body<0>(g_attn, Wo, bo, out, blockIdx.x, blockIdx.y);
}

// ===========================================================================
// Flash attention, tf32 mma.sync, fragment-packed smem, double-buffered K/V.
// smem words: Q[8][8][32]x4 = 8192 | per buf: K[8][8][32]x2 = 4096, V same.
// Total = 8192 + 2*8192 = 24576 words = 96KB.
// ===========================================================================
#define ATTN_SMEM (24576 * 4)

__global__ __launch_bounds__(256) void attn_kernel()
{
    extern __shared__ unsigned smq[];

    const int tid  = threadIdx.x;
    const int lane = tid & 31, wid = tid >> 5;
    const int g = lane >> 2, t = lane & 3;
    const int bh = blockIdx.y, q0 = blockIdx.x * 128;
    const float* Qg = g_q + (size_t)bh * TSEQ * HDI;
    const float* Kg = g_k + (size_t)bh * TSEQ * HDI;
    const float* Vg = g_v + (size_t)bh * TSEQ * HDI;

    // ---- stage Q (fragment layout, scaled by 1/8) ----
    {
        int row = tid >> 1, c0 = (tid & 1) * 32;
#pragma unroll
        for (int i = 0; i < 8; i++) {
            int c = c0 + 4 * i;
            float4 v = *(const float4*)(Qg + (size_t)(q0 + row) * HDI + c);
            int ks = c >> 3, h = (c >> 2) & 1;
            unsigned* p = smq + ((row >> 4) * 8 + ks) * 128 + (row & 7) * 16
                              + h * 2 + ((row >> 3) & 1);
            p[0]  = f2tf(v.x * 0.125f); p[4]  = f2tf(v.y * 0.125f);
            p[8]  = f2tf(v.z * 0.125f); p[12] = f2tf(v.w * 0.125f);
        }
    }

    // ---- K/V staging geometry ----
    const int krow = tid >> 2, kc0 = (tid & 3) * 16;
    unsigned kbase[4], vbase[4];
#pragma unroll
    for (int i = 0; i < 4; i++) {
        int c = kc0 + 4 * i;
        int ks = c >> 3, h = (c >> 2) & 1;
        kbase[i] = ((krow >> 3) * 8 + ks) * 64 + (krow & 7) * 8 + h;
        // V: element (j=krow, d=c+jj): tile=(d>>3)*8 + (j>>3); lane=(d&7)*4+(j&3)
        vbase[i] = 4096 + ((c >> 3) * 8 + (krow >> 3)) * 64
                        + ((c & 7) * 4 + (krow & 3)) * 2 + ((krow >> 2) & 1);
    }

    float4 rk[4], rv[4];
#pragma unroll
    for (int i = 0; i < 4; i++) {
        rk[i] = *(const float4*)(Kg + (size_t)krow * HDI + kc0 + 4 * i);
        rv[i] = *(const float4*)(Vg + (size_t)krow * HDI + kc0 + 4 * i);
    }
    {
        unsigned* dst = smq + 8192;
#pragma unroll
        for (int i = 0; i < 4; i++) {
            unsigned* pk = dst + kbase[i];
            pk[0] = f2tf(rk[i].x); pk[2] = f2tf(rk[i].y);
            pk[4] = f2tf(rk[i].z); pk[6] = f2tf(rk[i].w);
            unsigned* pv = dst + vbase[i];
            pv[0] = f2tf(rv[i].x); pv[8] = f2tf(rv[i].y);
            pv[16] = f2tf(rv[i].z); pv[24] = f2tf(rv[i].w);
        }
    }
    __syncthreads();

    float o[8][4];
#pragma unroll
    for (int nt = 0; nt < 8; nt++)
#pragma unroll
        for (int f = 0; f < 4; f++) o[nt][f] = 0.f;
    float m0r = -1e30f, m1r = -1e30f, l0 = 0.f, l1 = 0.f;

    const int lo = (lane & ~3) | (t >> 1);
    const int hi = lo + 2;
    const bool odd = (t & 1);

    for (int jb = 0; jb < 32; jb++) {
        const int b = jb & 1;
        if (jb < 31) {
            const float* nK = Kg + (size_t)((jb + 1) * 64 + krow) * HDI + kc0;
            const float* nV = Vg + (size_t)((jb + 1) * 64 + krow) * HDI + kc0;
#pragma unroll
            for (int i = 0; i < 4; i++) { rk[i] = *(const float4*)(nK + 4 * i);
                                          rv[i] = *(const float4*)(nV + 4 * i); }
        }
        const uint2* Kv = (const uint2*)(smq + 8192 + b * 8192);
        const uint2* Vv = (const uint2*)(smq + 8192 + b * 8192 + 4096);
        const uint4* Qv = (const uint4*)smq;

        // S = (Q/8) K^T
        float s[8][4];
#pragma unroll
        for (int nt = 0; nt < 8; nt++)
#pragma unroll
            for (int f = 0; f < 4; f++) s[nt][f] = 0.f;
#pragma unroll
        for (int ks = 0; ks < 8; ks++) {
            uint4 a4 = Qv[(wid * 8 + ks) * 32 + lane];
            unsigned af[4] = {a4.x, a4.y, a4.z, a4.w};
#pragma unroll
            for (int nt = 0; nt < 8; nt++) {
                uint2 bb = Kv[(nt * 8 + ks) * 32 + lane];
                unsigned bf[2] = {bb.x, bb.y};
                mma8(s[nt], af, bf);
            }
        }

        // Online softmax
        float mx0 = -1e30f, mx1 = -1e30f;
#pragma unroll
        for (int nt = 0; nt < 8; nt++) {
            mx0 = fmaxf(mx0, fmaxf(s[nt][0], s[nt][1]));
            mx1 = fmaxf(mx1, fmaxf(s[nt][2], s[nt][3]));
        }
#pragma unroll
        for (int off = 1; off <= 2; off <<= 1) {
            mx0 = fmaxf(mx0, __shfl_xor_sync(0xffffffffu, mx0, off));
            mx1 = fmaxf(mx1, __shfl_xor_sync(0xffffffffu, mx1, off));
        }
        float M0 = fmaxf(m0r, mx0), M1 = fmaxf(m1r, mx1);
        float al0 = __expf(m0r - M0), al1 = __expf(m1r - M1);
        float rs0 = 0.f, rs1 = 0.f;
#pragma unroll
        for (int nt = 0; nt < 8; nt++) {
            s[nt][0] = __expf(s[nt][0] - M0); rs0 += s[nt][0];
            s[nt][1] = __expf(s[nt][1] - M0); rs0 += s[nt][1];
            s[nt][2] = __expf(s[nt][2] - M1); rs1 += s[nt][2];
            s[nt][3] = __expf(s[nt][3] - M1); rs1 += s[nt][3];
        }
#pragma unroll
        for (int off = 1; off <= 2; off <<= 1) {
            rs0 += __shfl_xor_sync(0xffffffffu, rs0, off);
            rs1 += __shfl_xor_sync(0xffffffffu, rs1, off);
        }
        l0 = l0 * al0 + rs0; l1 = l1 * al1 + rs1;
        m0r = M0; m1r = M1;
#pragma unroll
        for (int nt = 0; nt < 8; nt++) {
            o[nt][0] *= al0; o[nt][1] *= al0;
            o[nt][2] *= al1; o[nt][3] *= al1;
        }

        // O += P V ; P via 4-lane shuffles into A-fragments
#pragma unroll
        for (int ks = 0; ks < 8; ks++) {
            float p0 = __shfl_sync(0xffffffffu, s[ks][0], lo);
            float p1 = __shfl_sync(0xffffffffu, s[ks][1], lo);
            float q0f = __shfl_sync(0xffffffffu, s[ks][0], hi);
            float q1f = __shfl_sync(0xffffffffu, s[ks][1], hi);
            float r0 = __shfl_sync(0xffffffffu, s[ks][2], lo);
            float r1 = __shfl_sync(0xffffffffu, s[ks][3], lo);
            float u0 = __shfl_sync(0xffffffffu, s[ks][2], hi);
            float u1 = __shfl_sync(0xffffffffu, s[ks][3], hi);
            unsigned af[4];
            af[0] = f2tf(odd ? p1 : p0);
            af[1] = f2tf(odd ? r1 : r0);
            af[2] = f2tf(odd ? q1f : q0f);
            af[3] = f2tf(odd ? u1 : u0);
#pragma unroll
            for (int nt = 0; nt < 8; nt++) {
                uint2 bb = Vv[(nt * 8 + ks) * 32 + lane];
                unsigned bf[2] = {bb.x, bb.y};
                mma8(o[nt], af, bf);
            }
        }

        if (jb < 31) {
            unsigned* dst = smq + 8192 + ((jb + 1) & 1) * 8192;
#pragma unroll
            for (int i = 0; i < 4; i++) {
                unsigned* pk = dst + kbase[i];
                pk[0] = f2tf(rk[i].x); pk[2] = f2tf(rk[i].y);
                pk[4] = f2tf(rk[i].z); pk[6] = f2tf(rk[i].w);
                unsigned* pv = dst + vbase[i];
                pv[0] = f2tf(rv[i].x); pv[8] = f2tf(rv[i].y);
                pv[16] = f2tf(rv[i].z); pv[24] = f2tf(rv[i].w);
            }
        }
        __syncthreads();
    }

    // Write back: [B,T,EMB] row-major for out-proj
    const int b = bh >> 4, h = bh & 15;
    float inv0 = 1.f / l0, inv1 = 1.f / l1;
    int r0 = q0 + wid * 16 + g, r1 = r0 + 8;
#pragma unroll
    for (int nt = 0; nt < 8; nt++) {
        int c = h * HDI + nt * 8 + 2 * t;
        *(float2*)(g_attn + (size_t)(b * TSEQ + r0) * EMBD + c)
            = make_float2(o[nt][0] * inv0, o[nt][1] * inv0);
        *(float2*)(g_attn + (size_t)(b * TSEQ + r1) * EMBD + c)
            = make_float2(o[nt][2] * inv1, o[nt][3] * inv1);
    }
}

// ---------------------------------------------------------------------------
extern "C" void kernel_launch(void* const* d_in, const int* in_sizes, int n_in,
                              void* d_out, int out_size)
{
    const float* x  = (const float*)d_in[0];
    const float* Wq = (const float*)d_in[1];
    const float* bq = (const float*)d_in[2];
    const float* Wk = (const float*)d_in[3];
    const float* bk = (const float*)d_in[4];
    const float* Wv = (const float*)d_in[5];
    const float* bv = (const float*)d_in[6];
    const float* Wo = (const float*)d_in[7];
    const float* bo = (const float*)d_in[8];
    float* out = (float*)d_out;

    static int inited = 0;
    if (!inited) {
        cudaFuncSetAttribute(qkv_kernel,  cudaFuncAttributeMaxDynamicSharedMemorySize, GEMM_SMEM);
        cudaFuncSetAttribute(proj_kernel, cudaFuncAttributeMaxDynamicSharedMemorySize, GEMM_SMEM);
        cudaFuncSetAttribute(attn_kernel, cudaFuncAttributeMaxDynamicSharedMemorySize, ATTN_SMEM);
        inited = 1;
    }

    dim3 gq(M_TOT / 128, EMBD / 128, 3);
    qkv_kernel<<<gq, 256, GEMM_SMEM>>>(x, Wq, bq, Wk, bk, Wv, bv);

    dim3 ga(TSEQ / 128, NB * NH);
    attn_kernel<<<ga, 256, ATTN_SMEM>>>();

    dim3 go(M_TOT / 128, EMBD / 128);
    proj_kernel<<<go, 256, GEMM_SMEM>>>(Wo, bo, out);
}

// round 6
// speedup vs baseline: 1.7784x; 1.7784x over previous
#include <cuda_runtime.h>
#include <cuda_fp16.h>
#include <cstdint>

#define M_TOT 8192
#define EMBD  1024
#define TSEQ  2048
#define NB    4
#define NH    16
#define HDI   64

// Scratch
__device__ float g_q[M_TOT * EMBD];
__device__ float g_k[M_TOT * EMBD];
__device__ float g_v[M_TOT * EMBD];
__device__ float g_attn[M_TOT * EMBD];

__device__ __forceinline__ unsigned h2(float a, float b) {
    __half2 h = __floats2half2_rn(a, b);
    return *(unsigned*)&h;
}

// D += A*B, m16n8k16 f16 -> f32, D==C in place
__device__ __forceinline__ void mma16(float* d, const unsigned* a, const unsigned* b) {
    asm volatile("mma.sync.aligned.m16n8k16.row.col.f32.f16.f16.f32 "
        "{%0,%1,%2,%3}, {%4,%5,%6,%7}, {%8,%9}, {%0,%1,%2,%3};"
        : "+f"(d[0]), "+f"(d[1]), "+f"(d[2]), "+f"(d[3])
        : "r"(a[0]), "r"(a[1]), "r"(a[2]), "r"(a[3]), "r"(b[0]), "r"(b[1]));
}

// ===========================================================================
// fp16 GEMM: Y = X @ W^T + bias.  128x128x32 tiles, 256 thr, 8 warps (4m x 2n),
// warp tile 32x64. Smem rows: 16 half2-words + pad -> stride 20 words.
// Bank for consumer LDS = (20r + w) % 32 -> all 32 lanes distinct.
// Double buffered, 1 sync per chunk. Stage = A(2560w) + B(2560w) = 20KB.
// ===========================================================================
#define GEMM_SMEM (2 * 5120 * 4)

template<int SCATTER>
__device__ __forceinline__ void gemm_body(
    const float* __restrict__ A, const float* __restrict__ Bw,
    const float* __restrict__ bias, float* __restrict__ out,
    int bx, int by)
{
    extern __shared__ unsigned smu[];   // [2][5120] words

    const int tid  = threadIdx.x;
    const int lane = tid & 31, wid = tid >> 5;
    const int g = lane >> 2, t = lane & 3;
    const int wm = (wid & 3) * 32, wn = (wid >> 2) * 64;
    const int m0 = bx * 128, n0 = by * 128;

    // Staging: thread covers row=tid>>1, 16 floats at (tid&1)*16.
    const int row = tid >> 1, cg = (tid & 1) * 16;
    const float* gA = A  + (size_t)(m0 + row) * EMBD + cg;
    const float* gB = Bw + (size_t)(n0 + row) * EMBD + cg;
    const unsigned sbase = row * 20 + (tid & 1) * 8;   // word offset (16B aligned)

    float4 ra[4], rb[4];
#pragma unroll
    for (int i = 0; i < 4; i++) { ra[i] = *(const float4*)(gA + 4 * i);
                                  rb[i] = *(const float4*)(gB + 4 * i); }

    // STS chunk 0 -> buf 0
    {
        unsigned aw[8], bw[8];
#pragma unroll
        for (int i = 0; i < 4; i++) {
            aw[2*i] = h2(ra[i].x, ra[i].y); aw[2*i+1] = h2(ra[i].z, ra[i].w);
            bw[2*i] = h2(rb[i].x, rb[i].y); bw[2*i+1] = h2(rb[i].z, rb[i].w);
        }
        uint4* pa = (uint4*)(smu + sbase);
        pa[0] = make_uint4(aw[0], aw[1], aw[2], aw[3]);
        pa[1] = make_uint4(aw[4], aw[5], aw[6], aw[7]);
        uint4* pb = (uint4*)(smu + 2560 + sbase);
        pb[0] = make_uint4(bw[0], bw[1], bw[2], bw[3]);
        pb[1] = make_uint4(bw[4], bw[5], bw[6], bw[7]);
    }
    __syncthreads();

    float acc[2][8][4];
#pragma unroll
    for (int mt = 0; mt < 2; mt++)
#pragma unroll
        for (int nt = 0; nt < 8; nt++)
#pragma unroll
            for (int f = 0; f < 4; f++) acc[mt][nt][f] = 0.f;

    for (int c = 0; c < 32; c++) {
        if (c < 31) {
            const float* nA = gA + (c + 1) * 32;
            const float* nB = gB + (c + 1) * 32;
#pragma unroll
            for (int i = 0; i < 4; i++) { ra[i] = *(const float4*)(nA + 4 * i);
                                          rb[i] = *(const float4*)(nB + 4 * i); }
        }
        const unsigned* Ab = smu + (c & 1) * 5120;
        const unsigned* Bb = Ab + 2560;
#pragma unroll
        for (int ks = 0; ks < 2; ks++) {
            const int kw = ks * 8 + t;
            unsigned af[2][4];
#pragma unroll
            for (int mt = 0; mt < 2; mt++) {
                int r = wm + mt * 16 + g;
                af[mt][0] = Ab[r * 20 + kw];
                af[mt][1] = Ab[(r + 8) * 20 + kw];
                af[mt][2] = Ab[r * 20 + kw + 4];
                af[mt][3] = Ab[(r + 8) * 20 + kw + 4];
            }
#pragma unroll
            for (int nt = 0; nt < 8; nt++) {
                int cc = wn + nt * 8 + g;
                unsigned bf[2];
                bf[0] = Bb[cc * 20 + kw];
                bf[1] = Bb[cc * 20 + kw + 4];
                mma16(acc[0][nt], af[0], bf);
                mma16(acc[1][nt], af[1], bf);
            }
        }
        if (c < 31) {
            unsigned* dst = smu + ((c + 1) & 1) * 5120;
            unsigned aw[8], bw[8];
#pragma unroll
            for (int i = 0; i < 4; i++) {
                aw[2*i] = h2(ra[i].x, ra[i].y); aw[2*i+1] = h2(ra[i].z, ra[i].w);
                bw[2*i] = h2(rb[i].x, rb[i].y); bw[2*i+1] = h2(rb[i].z, rb[i].w);
            }
            uint4* pa = (uint4*)(dst + sbase);
            pa[0] = make_uint4(aw[0], aw[1], aw[2], aw[3]);
            pa[1] = make_uint4(aw[4], aw[5], aw[6], aw[7]);
            uint4* pb = (uint4*)(dst + 2560 + sbase);
            pb[0] = make_uint4(bw[0], bw[1], bw[2], bw[3]);
            pb[1] = make_uint4(bw[4], bw[5], bw[6], bw[7]);
        }
        __syncthreads();
    }

    // Epilogue
#pragma unroll
    for (int mt = 0; mt < 2; mt++) {
        int rbase = m0 + wm + mt * 16 + g;
#pragma unroll
        for (int half = 0; half < 2; half++) {
            int r = rbase + half * 8;
            int bb2 = r >> 11, tt = r & 2047;
#pragma unroll
            for (int nt = 0; nt < 8; nt++) {
                int ccol = n0 + wn + nt * 8 + 2 * t;
                float v0 = acc[mt][nt][half * 2 + 0] + bias[ccol];
                float v1 = acc[mt][nt][half * 2 + 1] + bias[ccol + 1];
                if (SCATTER) {
                    int h = ccol >> 6, d = ccol & 63;
                    *(float2*)(out + ((size_t)((bb2 * NH + h) * TSEQ + tt)) * HDI + d)
                        = make_float2(v0, v1);
                } else {
                    *(float2*)(out + (size_t)r * EMBD + ccol) = make_float2(v0, v1);
                }
            }
        }
    }
}

__global__ __launch_bounds__(256) void qkv_kernel(
    const float* __restrict__ X,
    const float* __restrict__ Wq, const float* __restrict__ bq,
    const float* __restrict__ Wk, const float* __restrict__ bk,
    const float* __restrict__ Wv, const float* __restrict__ bv)
{
    const float* W; const float* bias; float* out;
    if (blockIdx.z == 0)      { W = Wq; bias = bq; out = g_q; }
    else if (blockIdx.z == 1) { W = Wk; bias = bk; out = g_k; }
    else                      { W = Wv; bias = bv; out = g_v; }
    gemm_body<1>(X, W, bias, out, blockIdx.x, blockIdx.y);
}

__global__ __launch_bounds__(256) void proj_kernel(
    const float* __restrict__ Wo, const float* __restrict__ bo,
    float* __restrict__ out)
{
    gemm_body<0>(g_attn, Wo, bo, out, blockIdx.x, blockIdx.y);
}

// ===========================================================================
// Flash attention, fp16 m16n8k16. 128 q-rows (8 warps x 16), key blocks of 64.
// Smem (words): Q[128][36] = 4608 | per stage: K[64][36]=2304, Vt[64][36]=2304.
// Q/K rows hold 32 half2-words (d-pairs); Vt rows are d with j-pairs.
// P: S-regs -> half2 -> A-frag directly (C-frag pairs == A-frag pairs). No shfl.
// ===========================================================================
#define ATTN_SMEM ((4608 + 2 * 4608) * 4)

__global__ __launch_bounds__(256) void attn_kernel()
{
    extern __shared__ unsigned smq[];
    unsigned* Qs = smq;

    const int tid  = threadIdx.x;
    const int lane = tid & 31, wid = tid >> 5;
    const int g = lane >> 2, t = lane & 3;
    const int bh = blockIdx.y, q0 = blockIdx.x * 128;
    const float* Qg = g_q + (size_t)bh * TSEQ * HDI;
    const float* Kg = g_k + (size_t)bh * TSEQ * HDI;
    const float* Vg = g_v + (size_t)bh * TSEQ * HDI;

    // ---- stage Q (scaled by 1/8): row=tid>>1, 32 floats at (tid&1)*32 ----
    {
        int row = tid >> 1, c0 = (tid & 1) * 32;
        unsigned qw[16];
#pragma unroll
        for (int i = 0; i < 8; i++) {
            float4 v = *(const float4*)(Qg + (size_t)(q0 + row) * HDI + c0 + 4 * i);
            qw[2*i]   = h2(v.x * 0.125f, v.y * 0.125f);
            qw[2*i+1] = h2(v.z * 0.125f, v.w * 0.125f);
        }
        uint4* p = (uint4*)(Qs + row * 36 + (tid & 1) * 16);
#pragma unroll
        for (int i = 0; i < 4; i++)
            p[i] = make_uint4(qw[4*i], qw[4*i+1], qw[4*i+2], qw[4*i+3]);
    }

    // ---- K/V staging geometry ----
    const int kj = tid >> 2, kd0 = (tid & 3) * 16;          // K: row j, 16 floats
    const int vjp = lane, vd0 = wid * 8;                     // V: j-pair, 8 d

    float4 rk[4], rv[4];
#pragma unroll
    for (int i = 0; i < 4; i++)
        rk[i] = *(const float4*)(Kg + (size_t)kj * HDI + kd0 + 4 * i);
    {
        const float* v0p = Vg + (size_t)(2 * vjp) * HDI + vd0;
        const float* v1p = Vg + (size_t)(2 * vjp + 1) * HDI + vd0;
        rv[0] = *(const float4*)(v0p); rv[1] = *(const float4*)(v0p + 4);
        rv[2] = *(const float4*)(v1p); rv[3] = *(const float4*)(v1p + 4);
    }
    {
        unsigned* Kb = smq + 4608;
        unsigned kw[8];
#pragma unroll
        for (int i = 0; i < 4; i++) {
            kw[2*i] = h2(rk[i].x, rk[i].y); kw[2*i+1] = h2(rk[i].z, rk[i].w);
        }
        uint4* pk = (uint4*)(Kb + kj * 36 + (tid & 3) * 8);
        pk[0] = make_uint4(kw[0], kw[1], kw[2], kw[3]);
        pk[1] = make_uint4(kw[4], kw[5], kw[6], kw[7]);
        unsigned* Vb = Kb + 2304;
        const float* f0 = (const float*)&rv[0];
        const float* f1 = (const float*)&rv[2];
#pragma unroll
        for (int i = 0; i < 8; i++)
            Vb[(vd0 + i) * 36 + vjp] = h2(f0[i], f1[i]);
    }
    __syncthreads();

    float o[8][4];
#pragma unroll
    for (int nt = 0; nt < 8; nt++)
#pragma unroll
        for (int f = 0; f < 4; f++) o[nt][f] = 0.f;
    float m0r = -1e30f, m1r = -1e30f, l0 = 0.f, l1 = 0.f;

    for (int jb = 0; jb < 32; jb++) {
        if (jb < 31) {
            const float* nK = Kg + (size_t)((jb + 1) * 64 + kj) * HDI + kd0;
#pragma unroll
            for (int i = 0; i < 4; i++) rk[i] = *(const float4*)(nK + 4 * i);
            const float* v0p = Vg + (size_t)((jb + 1) * 64 + 2 * vjp) * HDI + vd0;
            const float* v1p = v0p + HDI;
            rv[0] = *(const float4*)(v0p); rv[1] = *(const float4*)(v0p + 4);
            rv[2] = *(const float4*)(v1p); rv[3] = *(const float4*)(v1p + 4);
        }
        const unsigned* Kb = smq + 4608 + (jb & 1) * 4608;
        const unsigned* Vb = Kb + 2304;

        // S = (Q/8) K^T : 4 k-steps x 8 n-tiles
        float s[8][4];
#pragma unroll
        for (int nt = 0; nt < 8; nt++)
#pragma unroll
            for (int f = 0; f < 4; f++) s[nt][f] = 0.f;
#pragma unroll
        for (int ks = 0; ks < 4; ks++) {
            const int kw = ks * 8 + t;
            unsigned af[4];
            int r = wid * 16 + g;
            af[0] = Qs[r * 36 + kw];
            af[1] = Qs[(r + 8) * 36 + kw];
            af[2] = Qs[r * 36 + kw + 4];
            af[3] = Qs[(r + 8) * 36 + kw + 4];
#pragma unroll
            for (int nt = 0; nt < 8; nt++) {
                unsigned bf[2];
                bf[0] = Kb[(nt * 8 + g) * 36 + kw];
                bf[1] = Kb[(nt * 8 + g) * 36 + kw + 4];
                mma16(s[nt], af, bf);
            }
        }

        // Online softmax
        float mx0 = -1e30f, mx1 = -1e30f;
#pragma unroll
        for (int nt = 0; nt < 8; nt++) {
            mx0 = fmaxf(mx0, fmaxf(s[nt][0], s[nt][1]));
            mx1 = fmaxf(mx1, fmaxf(s[nt][2], s[nt][3]));
        }
#pragma unroll
        for (int off = 1; off <= 2; off <<= 1) {
            mx0 = fmaxf(mx0, __shfl_xor_sync(0xffffffffu, mx0, off));
            mx1 = fmaxf(mx1, __shfl_xor_sync(0xffffffffu, mx1, off));
        }
        float M0 = fmaxf(m0r, mx0), M1 = fmaxf(m1r, mx1);
        float al0 = __expf(m0r - M0), al1 = __expf(m1r - M1);
        float rs0 = 0.f, rs1 = 0.f;
#pragma unroll
        for (int nt = 0; nt < 8; nt++) {
            s[nt][0] = __expf(s[nt][0] - M0); rs0 += s[nt][0];
            s[nt][1] = __expf(s[nt][1] - M0); rs0 += s[nt][1];
            s[nt][2] = __expf(s[nt][2] - M1); rs1 += s[nt][2];
            s[nt][3] = __expf(s[nt][3] - M1); rs1 += s[nt][3];
        }
#pragma unroll
        for (int off = 1; off <= 2; off <<= 1) {
            rs0 += __shfl_xor_sync(0xffffffffu, rs0, off);
            rs1 += __shfl_xor_sync(0xffffffffu, rs1, off);
        }
        l0 = l0 * al0 + rs0; l1 = l1 * al1 + rs1;
        m0r = M0; m1r = M1;
#pragma unroll
        for (int nt = 0; nt < 8; nt++) {
            o[nt][0] *= al0; o[nt][1] *= al0;
            o[nt][2] *= al1; o[nt][3] *= al1;
        }

        // O += P V : P C-frag pairs map directly onto A-frag pairs
#pragma unroll
        for (int ks = 0; ks < 4; ks++) {
            unsigned af[4];
            af[0] = h2(s[2*ks][0],   s[2*ks][1]);
            af[1] = h2(s[2*ks][2],   s[2*ks][3]);
            af[2] = h2(s[2*ks+1][0], s[2*ks+1][1]);
            af[3] = h2(s[2*ks+1][2], s[2*ks+1][3]);
            const int kw = ks * 8 + t;
#pragma unroll
            for (int nt = 0; nt < 8; nt++) {
                unsigned bf[2];
                bf[0] = Vb[(nt * 8 + g) * 36 + kw];
                bf[1] = Vb[(nt * 8 + g) * 36 + kw + 4];
                mma16(o[nt], af, bf);
            }
        }

        if (jb < 31) {
            unsigned* Kd = smq + 4608 + ((jb + 1) & 1) * 4608;
            unsigned kw[8];
#pragma unroll
            for (int i = 0; i < 4; i++) {
                kw[2*i] = h2(rk[i].x, rk[i].y); kw[2*i+1] = h2(rk[i].z, rk[i].w);
            }
            uint4* pk = (uint4*)(Kd + kj * 36 + (tid & 3) * 8);
            pk[0] = make_uint4(kw[0], kw[1], kw[2], kw[3]);
            pk[1] = make_uint4(kw[4], kw[5], kw[6], kw[7]);
            unsigned* Vd = Kd + 2304;
            const float* f0 = (const float*)&rv[0];
            const float* f1 = (const float*)&rv[2];
#pragma unroll
            for (int i = 0; i < 8; i++)
                Vd[(vd0 + i) * 36 + vjp] = h2(f0[i], f1[i]);
        }
        __syncthreads();
    }

    // Write back: [B,T,EMB] row-major for out-proj
    const int b = bh >> 4, h = bh & 15;
    float inv0 = 1.f / l0, inv1 = 1.f / l1;
    int r0 = q0 + wid * 16 + g, r1 = r0 + 8;
#pragma unroll
    for (int nt = 0; nt < 8; nt++) {
        int c = h * HDI + nt * 8 + 2 * t;
        *(float2*)(g_attn + (size_t)(b * TSEQ + r0) * EMBD + c)
            = make_float2(o[nt][0] * inv0, o[nt][1] * inv0);
        *(float2*)(g_attn + (size_t)(b * TSEQ + r1) * EMBD + c)
            = make_float2(o[nt][2] * inv1, o[nt][3] * inv1);
    }
}

// ---------------------------------------------------------------------------
extern "C" void kernel_launch(void* const* d_in, const int* in_sizes, int n_in,
                              void* d_out, int out_size)
{
    const float* x  = (const float*)d_in[0];
    const float* Wq = (const float*)d_in[1];
    const float* bq = (const float*)d_in[2];
    const float* Wk = (const float*)d_in[3];
    const float* bk = (const float*)d_in[4];
    const float* Wv = (const float*)d_in[5];
    const float* bv = (const float*)d_in[6];
    const float* Wo = (const float*)d_in[7];
    const float* bo = (const float*)d_in[8];
    float* out = (float*)d_out;

    static int inited = 0;
    if (!inited) {
        cudaFuncSetAttribute(qkv_kernel,  cudaFuncAttributeMaxDynamicSharedMemorySize, GEMM_SMEM);
        cudaFuncSetAttribute(proj_kernel, cudaFuncAttributeMaxDynamicSharedMemorySize, GEMM_SMEM);
        cudaFuncSetAttribute(attn_kernel, cudaFuncAttributeMaxDynamicSharedMemorySize, ATTN_SMEM);
        inited = 1;
    }

    dim3 gq(M_TOT / 128, EMBD / 128, 3);
    qkv_kernel<<<gq, 256, GEMM_SMEM>>>(x, Wq, bq, Wk, bk, Wv, bv);

    dim3 ga(TSEQ / 128, NB * NH);
    attn_kernel<<<ga, 256, ATTN_SMEM>>>();

    dim3 go(M_TOT / 128, EMBD / 128);
    proj_kernel<<<go, 256, GEMM_SMEM>>>(Wo, bo, out);
}

// round 7
// speedup vs baseline: 3.5501x; 1.9962x over previous
#include <cuda_runtime.h>
#include <cuda_fp16.h>
#include <cstdint>

#define M_TOT 8192
#define EMBD  1024
#define TSEQ  2048
#define NB    4
#define NH    16
#define HDI   64

// fp16 scratch
__device__ __half g_xh[M_TOT * EMBD];
__device__ __half g_wq[EMBD * EMBD];
__device__ __half g_wk[EMBD * EMBD];
__device__ __half g_wv[EMBD * EMBD];
__device__ __half g_wo[EMBD * EMBD];
__device__ __half g_qh[M_TOT * EMBD];   // [B,H,T,hd], pre-scaled by 1/8
__device__ __half g_kh[M_TOT * EMBD];   // [B,H,T,hd]
__device__ __half g_vh[M_TOT * EMBD];   // [B,H,T,hd]
__device__ __half g_ah[M_TOT * EMBD];   // [B,T,E]

__device__ __forceinline__ unsigned h2(float a, float b) {
    __half2 h = __floats2half2_rn(a, b);
    return *(unsigned*)&h;
}
__device__ __forceinline__ void mma16(float* d, const unsigned* a, const unsigned* b) {
    asm volatile("mma.sync.aligned.m16n8k16.row.col.f32.f16.f16.f32 "
        "{%0,%1,%2,%3}, {%4,%5,%6,%7}, {%8,%9}, {%0,%1,%2,%3};"
        : "+f"(d[0]), "+f"(d[1]), "+f"(d[2]), "+f"(d[3])
        : "r"(a[0]), "r"(a[1]), "r"(a[2]), "r"(a[3]), "r"(b[0]), "r"(b[1]));
}
__device__ __forceinline__ void cp16(uint32_t dst, const void* src) {
    asm volatile("cp.async.cg.shared.global [%0], [%1], 16;" :: "r"(dst), "l"(src));
}
__device__ __forceinline__ void cpcommit() { asm volatile("cp.async.commit_group;"); }
template<int N> __device__ __forceinline__ void cpwait() {
    asm volatile("cp.async.wait_group %0;" :: "n"(N));
}
__device__ __forceinline__ void ldsm4(unsigned& r0, unsigned& r1, unsigned& r2,
                                      unsigned& r3, uint32_t a) {
    asm volatile("ldmatrix.sync.aligned.m8n8.x4.shared.b16 {%0,%1,%2,%3}, [%4];"
                 : "=r"(r0), "=r"(r1), "=r"(r2), "=r"(r3) : "r"(a));
}
__device__ __forceinline__ void ldsm4t(unsigned& r0, unsigned& r1, unsigned& r2,
                                       unsigned& r3, uint32_t a) {
    asm volatile("ldmatrix.sync.aligned.m8n8.x4.trans.shared.b16 {%0,%1,%2,%3}, [%4];"
                 : "=r"(r0), "=r"(r1), "=r"(r2), "=r"(r3) : "r"(a));
}

// ===========================================================================
// fp32 -> fp16 conversion of inputs (one pass, trivially BW-bound)
// ===========================================================================
__global__ __launch_bounds__(256) void cvt_all(
    const float* __restrict__ x, const float* __restrict__ wq,
    const float* __restrict__ wk, const float* __restrict__ wv,
    const float* __restrict__ wo)
{
    const float* src; __half* dst; int n;
    switch (blockIdx.y) {
        case 0:  src = x;  dst = g_xh; n = M_TOT * EMBD; break;
        case 1:  src = wq; dst = g_wq; n = EMBD * EMBD;  break;
        case 2:  src = wk; dst = g_wk; n = EMBD * EMBD;  break;
        case 3:  src = wv; dst = g_wv; n = EMBD * EMBD;  break;
        default: src = wo; dst = g_wo; n = EMBD * EMBD;  break;
    }
    int stride = gridDim.x * blockDim.x * 8;
    for (int i = (blockIdx.x * blockDim.x + threadIdx.x) * 8; i < n; i += stride) {
        float4 a = *(const float4*)(src + i);
        float4 b = *(const float4*)(src + i + 4);
        uint4 o;
        o.x = h2(a.x, a.y); o.y = h2(a.z, a.w);
        o.z = h2(b.x, b.y); o.w = h2(b.z, b.w);
        *(uint4*)(dst + i) = o;
    }
}

// ===========================================================================
// fp16 GEMM: Y = Xh @ Wh^T + bias.  128x128 tile, k-chunk 32, 4-stage cp.async.
// smem per stage: A[128][20w] + B[128][20w] = 20KB; 4 stages = 80KB.
// Consumer: ldmatrix.x4 (conflict-free: bank = 4r + k over 8 rows).
// ===========================================================================
#define GSTG 5120                   // words per stage
#define GEMM_SMEM (4 * GSTG * 4)    // 81920 B

template<int SCATTER>
__device__ __forceinline__ void gemm_body(
    const __half* __restrict__ A, const __half* __restrict__ Bw,
    const float* __restrict__ bias, void* __restrict__ outv,
    int bx, int by, float oscale)
{
    extern __shared__ unsigned smu[];
    const uint32_t sb = (uint32_t)__cvta_generic_to_shared(smu);

    const int tid  = threadIdx.x;
    const int lane = tid & 31, wid = tid >> 5;
    const int g = lane >> 2, t = lane & 3;
    const int wm = (wid & 3) * 32, wn = (wid >> 2) * 64;
    const int m0 = bx * 128, n0 = by * 128;

    // cp.async geometry: row = tid>>1, 16 halves at (tid&1)*16
    const int crow = tid >> 1, csel = tid & 1;
    const __half* gA = A  + (size_t)(m0 + crow) * EMBD + csel * 16;
    const __half* gB = Bw + (size_t)(n0 + crow) * EMBD + csel * 16;
    const uint32_t dA = sb + (crow * 20 + csel * 8) * 4;
    const uint32_t dB = dA + 2560 * 4;

    auto issue = [&](int c) {
        if (c < 32) {
            uint32_t so = (uint32_t)(c & 3) * (GSTG * 4);
            const __half* sa = gA + c * 32;
            const __half* sbp = gB + c * 32;
            cp16(dA + so, sa);       cp16(dA + so + 16, sa + 8);
            cp16(dB + so, sbp);      cp16(dB + so + 16, sbp + 8);
        }
        cpcommit();
    };
    issue(0); issue(1); issue(2);

    // ldmatrix lane addresses
    const uint32_t aAddr = sb +
        ((wm + (lane & 15)) * 20 + ((lane & 16) ? 4 : 0)) * 4;
    const uint32_t bAddr = sb + 2560 * 4 +
        ((wn + (lane & 7) + ((lane & 16) ? 8 : 0)) * 20 + ((lane & 8) ? 4 : 0)) * 4;

    float acc[2][8][4];
#pragma unroll
    for (int mt = 0; mt < 2; mt++)
#pragma unroll
        for (int nt = 0; nt < 8; nt++)
#pragma unroll
            for (int f = 0; f < 4; f++) acc[mt][nt][f] = 0.f;

    for (int c = 0; c < 32; c++) {
        cpwait<2>();
        __syncthreads();
        issue(c + 3);
        const uint32_t so = (uint32_t)(c & 3) * (GSTG * 4);
#pragma unroll
        for (int ks = 0; ks < 2; ks++) {
            unsigned af[2][4], bf[4][4];
            ldsm4(af[0][0], af[0][1], af[0][2], af[0][3], aAddr + so + ks * 32);
            ldsm4(af[1][0], af[1][1], af[1][2], af[1][3], aAddr + so + 16 * 80 + ks * 32);
#pragma unroll
            for (int np = 0; np < 4; np++)
                ldsm4(bf[np][0], bf[np][1], bf[np][2], bf[np][3],
                      bAddr + so + np * (16 * 80) + ks * 32);
#pragma unroll
            for (int mt = 0; mt < 2; mt++)
#pragma unroll
                for (int np = 0; np < 4; np++) {
                    mma16(acc[mt][2 * np + 0], af[mt], &bf[np][0]);
                    mma16(acc[mt][2 * np + 1], af[mt], &bf[np][2]);
                }
        }
    }

    // Epilogue
#pragma unroll
    for (int mt = 0; mt < 2; mt++) {
        int rbase = m0 + wm + mt * 16 + g;
#pragma unroll
        for (int half = 0; half < 2; half++) {
            int r = rbase + half * 8;
            int bb2 = r >> 11, tt = r & 2047;
#pragma unroll
            for (int nt = 0; nt < 8; nt++) {
                int ccol = n0 + wn + nt * 8 + 2 * t;
                float v0 = (acc[mt][nt][half * 2 + 0] + bias[ccol]) * oscale;
                float v1 = (acc[mt][nt][half * 2 + 1] + bias[ccol + 1]) * oscale;
                if (SCATTER) {
                    int h = ccol >> 6, d = ccol & 63;
                    __half* out = (__half*)outv;
                    *(unsigned*)(out + ((size_t)((bb2 * NH + h) * TSEQ + tt)) * HDI + d)
                        = h2(v0, v1);
                } else {
                    float* out = (float*)outv;
                    *(float2*)(out + (size_t)r * EMBD + ccol) = make_float2(v0, v1);
                }
            }
        }
    }
}

__global__ __launch_bounds__(256, 2) void qkv_kernel(
    const float* __restrict__ bq, const float* __restrict__ bk,
    const float* __restrict__ bv)
{
    const __half* W; const float* bias; __half* out; float sc;
    if (blockIdx.z == 0)      { W = g_wq; bias = bq; out = g_qh; sc = 0.125f; }
    else if (blockIdx.z == 1) { W = g_wk; bias = bk; out = g_kh; sc = 1.f; }
    else                      { W = g_wv; bias = bv; out = g_vh; sc = 1.f; }
    gemm_body<1>(g_xh, W, bias, out, blockIdx.x, blockIdx.y, sc);
}

__global__ __launch_bounds__(256, 2) void proj_kernel(
    const float* __restrict__ bo, float* __restrict__ out)
{
    gemm_body<0>(g_ah, g_wo, bo, out, blockIdx.x, blockIdx.y, 1.f);
}

// ===========================================================================
// Flash attention fp16. 128 q-rows/CTA (8 warps x 16), key blocks 64, 3-stage
// cp.async K/V pipeline. Q fragments hoisted to registers for all 32 blocks.
// smem words: Q[128][36]=4608 | stage s: K[64][36]=2304, V[64][36]=2304.
// ===========================================================================
#define ASTG 4608
#define ATTN_SMEM ((4608 + 3 * ASTG) * 4)   // 73728 B

__global__ __launch_bounds__(256, 2) void attn_kernel()
{
    extern __shared__ unsigned smq[];
    const uint32_t sb = (uint32_t)__cvta_generic_to_shared(smq);

    const int tid  = threadIdx.x;
    const int lane = tid & 31, wid = tid >> 5;
    const int g = lane >> 2, t = lane & 3;
    const int bh = blockIdx.y, q0 = blockIdx.x * 128;
    const __half* Qg = g_qh + (size_t)bh * TSEQ * HDI;
    const __half* Kg = g_kh + (size_t)bh * TSEQ * HDI;
    const __half* Vg = g_vh + (size_t)bh * TSEQ * HDI;

    // cp.async geometry
    const int qrow = tid >> 1, qsel = tid & 1;               // Q: 2 thr/row, 4x16B
    const int krow = tid >> 2, ksel = tid & 3;               // K/V: 4 thr/row, 2x16B
    const uint32_t dQ = sb + (qrow * 36 + qsel * 16) * 4;
    const uint32_t dKo = (krow * 36 + ksel * 8) * 4;

    // group 0: Q + KV stage 0
    {
        const __half* sq = Qg + (size_t)(q0 + qrow) * HDI + qsel * 32;
        cp16(dQ, sq); cp16(dQ + 16, sq + 8);
        cp16(dQ + 32, sq + 16); cp16(dQ + 48, sq + 24);
    }
    auto issueKV = [&](int c) {
        if (c < 32) {
            uint32_t base = sb + (4608 + (c % 3) * ASTG) * 4;
            const __half* sk = Kg + (size_t)(c * 64 + krow) * HDI + ksel * 16;
            const __half* sv = Vg + (size_t)(c * 64 + krow) * HDI + ksel * 16;
            cp16(base + dKo, sk);               cp16(base + dKo + 16, sk + 8);
            cp16(base + 2304 * 4 + dKo, sv);    cp16(base + 2304 * 4 + dKo + 16, sv + 8);
        }
        cpcommit();
    };
    issueKV(0);   // completes group 0 (Q + KV0)
    issueKV(1);   // group 1

    // ldmatrix lane address components
    const uint32_t qAddr = sb +
        ((wid * 16 + (lane & 15)) * 36 + ((lane & 16) ? 4 : 0)) * 4;
    const uint32_t kLane =
        (((lane & 7) + ((lane & 16) ? 8 : 0)) * 36 + ((lane & 8) ? 4 : 0)) * 4;
    const uint32_t vLane =
        (((lane & 7) + ((lane & 8) ? 8 : 0)) * 36 + ((lane & 16) ? 4 : 0)) * 4;

    unsigned qa[4][4];
    float o[8][4];
#pragma unroll
    for (int nt = 0; nt < 8; nt++)
#pragma unroll
        for (int f = 0; f < 4; f++) o[nt][f] = 0.f;
    float m0r = -1e30f, m1r = -1e30f, l0 = 0.f, l1 = 0.f;

    for (int jb = 0; jb < 32; jb++) {
        cpwait<1>();
        __syncthreads();
        if (jb == 0) {
#pragma unroll
            for (int ks = 0; ks < 4; ks++)
                ldsm4(qa[ks][0], qa[ks][1], qa[ks][2], qa[ks][3], qAddr + ks * 32);
        }
        issueKV(jb + 2);

        const uint32_t kBase = sb + (4608 + (jb % 3) * ASTG) * 4 + kLane;
        const uint32_t vBase = sb + (4608 + (jb % 3) * ASTG + 2304) * 4 + vLane;

        // S = (Q/8) K^T
        float s[8][4];
#pragma unroll
        for (int nt = 0; nt < 8; nt++)
#pragma unroll
            for (int f = 0; f < 4; f++) s[nt][f] = 0.f;
#pragma unroll
        for (int ks = 0; ks < 4; ks++) {
            unsigned bf[4][4];
#pragma unroll
            for (int np = 0; np < 4; np++)
                ldsm4(bf[np][0], bf[np][1], bf[np][2], bf[np][3],
                      kBase + np * (16 * 36 * 4) + ks * 32);
#pragma unroll
            for (int np = 0; np < 4; np++) {
                mma16(s[2 * np + 0], qa[ks], &bf[np][0]);
                mma16(s[2 * np + 1], qa[ks], &bf[np][2]);
            }
        }

        // Online softmax
        float mx0 = -1e30f, mx1 = -1e30f;
#pragma unroll
        for (int nt = 0; nt < 8; nt++) {
            mx0 = fmaxf(mx0, fmaxf(s[nt][0], s[nt][1]));
            mx1 = fmaxf(mx1, fmaxf(s[nt][2], s[nt][3]));
        }
#pragma unroll
        for (int off = 1; off <= 2; off <<= 1) {
            mx0 = fmaxf(mx0, __shfl_xor_sync(0xffffffffu, mx0, off));
            mx1 = fmaxf(mx1, __shfl_xor_sync(0xffffffffu, mx1, off));
        }
        float M0 = fmaxf(m0r, mx0), M1 = fmaxf(m1r, mx1);
        float al0 = __expf(m0r - M0), al1 = __expf(m1r - M1);
        float rs0 = 0.f, rs1 = 0.f;
#pragma unroll
        for (int nt = 0; nt < 8; nt++) {
            s[nt][0] = __expf(s[nt][0] - M0); rs0 += s[nt][0];
            s[nt][1] = __expf(s[nt][1] - M0); rs0 += s[nt][1];
            s[nt][2] = __expf(s[nt][2] - M1); rs1 += s[nt][2];
            s[nt][3] = __expf(s[nt][3] - M1); rs1 += s[nt][3];
        }
#pragma unroll
        for (int off = 1; off <= 2; off <<= 1) {
            rs0 += __shfl_xor_sync(0xffffffffu, rs0, off);
            rs1 += __shfl_xor_sync(0xffffffffu, rs1, off);
        }
        l0 = l0 * al0 + rs0; l1 = l1 * al1 + rs1;
        m0r = M0; m1r = M1;
#pragma unroll
        for (int nt = 0; nt < 8; nt++) {
            o[nt][0] *= al0; o[nt][1] *= al0;
            o[nt][2] *= al1; o[nt][3] *= al1;
        }

        // O += P V  (P from S regs; V fragments via ldmatrix.trans)
#pragma unroll
        for (int ks = 0; ks < 4; ks++) {
            unsigned af[4];
            af[0] = h2(s[2 * ks][0],     s[2 * ks][1]);
            af[1] = h2(s[2 * ks][2],     s[2 * ks][3]);
            af[2] = h2(s[2 * ks + 1][0], s[2 * ks + 1][1]);
            af[3] = h2(s[2 * ks + 1][2], s[2 * ks + 1][3]);
#pragma unroll
            for (int np = 0; np < 4; np++) {
                unsigned vf[4];
                ldsm4t(vf[0], vf[1], vf[2], vf[3],
                       vBase + ks * (16 * 36 * 4) + np * 32);
                mma16(o[2 * np + 0], af, &vf[0]);
                mma16(o[2 * np + 1], af, &vf[2]);
            }
        }
    }

    // Write back fp16 [B,T,E]
    const int b = bh >> 4, h = bh & 15;
    float inv0 = 1.f / l0, inv1 = 1.f / l1;
    int r0 = q0 + wid * 16 + g, r1 = r0 + 8;
#pragma unroll
    for (int nt = 0; nt < 8; nt++) {
        int c = h * HDI + nt * 8 + 2 * t;
        *(unsigned*)(g_ah + (size_t)(b * TSEQ + r0) * EMBD + c)
            = h2(o[nt][0] * inv0, o[nt][1] * inv0);
        *(unsigned*)(g_ah + (size_t)(b * TSEQ + r1) * EMBD + c)
            = h2(o[nt][2] * inv1, o[nt][3] * inv1);
    }
}

// ---------------------------------------------------------------------------
extern "C" void kernel_launch(void* const* d_in, const int* in_sizes, int n_in,
                              void* d_out, int out_size)
{
    const float* x  = (const float*)d_in[0];
    const float* Wq = (const float*)d_in[1];
    const float* bq = (const float*)d_in[2];
    const float* Wk = (const float*)d_in[3];
    const float* bk = (const float*)d_in[4];
    const float* Wv = (const float*)d_in[5];
    const float* bv = (const float*)d_in[6];
    const float* Wo = (const float*)d_in[7];
    const float* bo = (const float*)d_in[8];
    float* out = (float*)d_out;

    static int inited = 0;
    if (!inited) {
        cudaFuncSetAttribute(qkv_kernel,  cudaFuncAttributeMaxDynamicSharedMemorySize, GEMM_SMEM);
        cudaFuncSetAttribute(proj_kernel, cudaFuncAttributeMaxDynamicSharedMemorySize, GEMM_SMEM);
        cudaFuncSetAttribute(attn_kernel, cudaFuncAttributeMaxDynamicSharedMemorySize, ATTN_SMEM);
        inited = 1;
    }

    cvt_all<<<dim3(128, 5), 256>>>(x, Wq, Wk, Wv, Wo);

    dim3 gq(M_TOT / 128, EMBD / 128, 3);
    qkv_kernel<<<gq, 256, GEMM_SMEM>>>(bq, bk, bv);

    dim3 ga(TSEQ / 128, NB * NH);
    attn_kernel<<<ga, 256, ATTN_SMEM>>>();

    dim3 go(M_TOT / 128, EMBD / 128);
    proj_kernel<<<go, 256, GEMM_SMEM>>>(bo, out);
}